// round 6
// baseline (speedup 1.0000x reference)
#include <cuda_runtime.h>

#define BB 2
#define LL 512
#define DD 256
#define NN 256
#define DT 64
#define PW 576   // DT + 2*DD
#define NP 128   // n-pairs per row
#define CC 8     // chunks
#define CL 64    // chunk length (LL/CC)

// scratch (device globals — no allocations allowed); +16 rows padding so the
// software pipeline can over-prefetch past the end without bounds checks.
__device__ float  g_proj[(BB * LL + 16) * PW];   // [row, 576] : dt_raw | beta | gamma
__device__ float2 g_ddx [(BB * LL + 16) * DD];   // {dt, dt*x} per (row, d)
__device__ float4 g_bg  [(BB * LL + 16) * NP];   // {be0, be1, ga0, ga1} per (row, n-pair)
__device__ float  g_xd  [(BB * LL + 16) * DD];   // x * delta
__device__ float  g_A2  [DD * NN];               // -exp(alpha_log) * log2(e)
__device__ float  g_cdt [BB * DD * LL];          // inclusive dt prefix within chunk, [(b*DD+d)*LL + l]
__device__ float  g_E   [BB * DD * CC * NN];     // local chunk end states
__device__ float  g_S   [BB * DD * CC * NN];     // true chunk initial states (c>=1)

__device__ __forceinline__ float ex2_approx(float x) {
    float r;
    asm("ex2.approx.ftz.f32 %0, %1;" : "=f"(r) : "f"(x));
    return r;
}

// ---------------------------------------------------------------------------
// Kernel 0: A2[d][n] = -exp(alpha_log[d][n]) * log2(e)
// ---------------------------------------------------------------------------
__global__ void a2_kernel(const float* __restrict__ alog) {
    int i = blockIdx.x * blockDim.x + threadIdx.x;
    if (i < DD * NN)
        g_A2[i] = -__expf(alog[i]) * 1.4426950408889634f;
}

// ---------------------------------------------------------------------------
// Kernel 1: proj = x @ W_in   ([1024,256] x [256,576] -> [1024,576])
// ---------------------------------------------------------------------------
__global__ void proj_kernel(const float* __restrict__ x, const float* __restrict__ W) {
    __shared__ float xs[32][33];
    __shared__ float ws[32][33];
    int row = blockIdx.y * 32 + threadIdx.y;
    int col = blockIdx.x * 32 + threadIdx.x;
    float acc = 0.f;
    for (int kt = 0; kt < DD; kt += 32) {
        xs[threadIdx.y][threadIdx.x] = x[row * DD + kt + threadIdx.x];
        ws[threadIdx.y][threadIdx.x] = W[(kt + threadIdx.y) * PW + col];
        __syncthreads();
#pragma unroll
        for (int k = 0; k < 32; k++)
            acc = fmaf(xs[threadIdx.y][k], ws[k][threadIdx.x], acc);
        __syncthreads();
    }
    g_proj[row * PW + col] = acc;
}

// ---------------------------------------------------------------------------
// Kernel 2: dt = softplus(proj[:, :64] @ W_dt + b_dt); pack {dt, dt*x}; xd
// ---------------------------------------------------------------------------
__global__ void dt_kernel(const float* __restrict__ x, const float* __restrict__ Wdt,
                          const float* __restrict__ bdt, const float* __restrict__ delta) {
    int r = blockIdx.x;
    int d = threadIdx.x;
    __shared__ float sp[DT];
    if (d < DT) sp[d] = g_proj[r * PW + d];
    __syncthreads();
    float acc = bdt[d];
#pragma unroll
    for (int k = 0; k < DT; k++)
        acc = fmaf(sp[k], Wdt[k * DD + d], acc);
    float dt = fmaxf(acc, 0.f) + log1pf(__expf(-fabsf(acc)));
    float xv = x[r * DD + d];
    int idx = r * DD + d;
    g_ddx[idx] = make_float2(dt, dt * xv);
    g_xd[idx]  = xv * delta[d];
}

// ---------------------------------------------------------------------------
// Kernel 2b: pack beta/gamma: g_bg[r][p] = {be[2p], be[2p+1], ga[2p], ga[2p+1]}
// ---------------------------------------------------------------------------
__global__ void pack_kernel() {
    int r = blockIdx.x;
    int p = threadIdx.x;       // 0..127 n-pair
    const float* pr = g_proj + (size_t)r * PW;
    float2 be = *(const float2*)(pr + DT + 2 * p);
    float2 ga = *(const float2*)(pr + DT + DD + 2 * p);
    g_bg[(size_t)r * NP + p] = make_float4(be.x, be.y, ga.x, ga.y);
}

// ---------------------------------------------------------------------------
// Kernel 2c: per-chunk inclusive dt prefix sums. One warp per (b, d).
// ---------------------------------------------------------------------------
__global__ void cdt_kernel() {
    const unsigned fm = 0xffffffffu;
    int warp = threadIdx.x >> 5;
    int lane = threadIdx.x & 31;
    int idx = blockIdx.x * 4 + warp;    // (b*DD + d)
    int b = idx >> 8;
    int d = idx & 255;

    float carry = 0.f;
    for (int lb = 0; lb < LL; lb += 32) {
        float v = g_ddx[(size_t)(b * LL + lb + lane) * DD + d].x;
#pragma unroll
        for (int off = 1; off < 32; off <<= 1) {
            float t = __shfl_up_sync(fm, v, off);
            if (lane >= off) v += t;
        }
        v += carry;
        g_cdt[(size_t)idx * LL + lb + lane] = v;
        float last = __shfl_sync(fm, v, 31);
        carry = ((lb + 32) & (CL - 1)) ? last : 0.f;   // reset at chunk boundary
    }
}

// ---------------------------------------------------------------------------
// Kernel 3 (pass B): local chunk scans (64 steps, zero init).
// One CTA per (b, d, c); 4 warps split n (2 per lane). Writes local y + xd
// to out and end states to g_E.
// ---------------------------------------------------------------------------

#define LOAD_BATCH(BUF, LB) do {                                              \
    _Pragma("unroll")                                                         \
    for (int k_ = 0; k_ < 8; k_++) {                                          \
        bg[BUF][k_] = bgp[(size_t)((LB) + k_) * NP];                          \
        dd[BUF][k_] = ddp[(size_t)((LB) + k_) * DD];                          \
    }                                                                         \
} while (0)

// transposed reduction over 32 lanes: Y[k]=sum_lanes yl_[k]; Y[lane&7] -> v_
#define TREDUCE8(YL, VOUT) do {                                               \
    float s_, r0_, r1_, r2_, r3_, q0_, q1_;                                   \
    s_  = bt0 ? YL[0] : YL[1];                                                \
    r0_ = (bt0 ? YL[1] : YL[0]) + __shfl_xor_sync(fm, s_, 1);                 \
    s_  = bt0 ? YL[2] : YL[3];                                                \
    r1_ = (bt0 ? YL[3] : YL[2]) + __shfl_xor_sync(fm, s_, 1);                 \
    s_  = bt0 ? YL[4] : YL[5];                                                \
    r2_ = (bt0 ? YL[5] : YL[4]) + __shfl_xor_sync(fm, s_, 1);                 \
    s_  = bt0 ? YL[6] : YL[7];                                                \
    r3_ = (bt0 ? YL[7] : YL[6]) + __shfl_xor_sync(fm, s_, 1);                 \
    s_  = bt1 ? r0_ : r1_;                                                    \
    q0_ = (bt1 ? r1_ : r0_) + __shfl_xor_sync(fm, s_, 2);                     \
    s_  = bt1 ? r2_ : r3_;                                                    \
    q1_ = (bt1 ? r3_ : r2_) + __shfl_xor_sync(fm, s_, 2);                     \
    s_  = bt2 ? q0_ : q1_;                                                    \
    VOUT = (bt2 ? q1_ : q0_) + __shfl_xor_sync(fm, s_, 4);                    \
    VOUT += __shfl_xor_sync(fm, VOUT, 8);                                     \
    VOUT += __shfl_xor_sync(fm, VOUT, 16);                                    \
} while (0)

#define COMPUTE_BATCH(BUF, LB) do {                                           \
    float yl_[8];                                                             \
    _Pragma("unroll")                                                         \
    for (int k_ = 0; k_ < 8; k_++) {                                          \
        float dt_  = dd[BUF][k_].x;                                           \
        float dtx_ = dd[BUF][k_].y;                                           \
        float a0_ = ex2_approx(dt_ * a2v0);                                   \
        float a1_ = ex2_approx(dt_ * a2v1);                                   \
        st0 = fmaf(a0_, st0, dtx_ * bg[BUF][k_].x);                           \
        st1 = fmaf(a1_, st1, dtx_ * bg[BUF][k_].y);                           \
        yl_[k_] = fmaf(st0, bg[BUF][k_].z, st1 * bg[BUF][k_].w);              \
    }                                                                         \
    float v_;                                                                 \
    TREDUCE8(yl_, v_);                                                        \
    if (lane < 8) ypart[warp * CL + (LB) + lane] = v_;                        \
} while (0)

__global__ void __launch_bounds__(128) scan_kernel(float* __restrict__ out) {
    __shared__ float ypart[4 * CL];

    const int warp = threadIdx.x >> 5;
    const int lane = threadIdx.x & 31;
    const int c  = blockIdx.x & 7;
    const int bd = blockIdx.x >> 3;
    const int b = bd >> 8;
    const int d = bd & 255;
    const int row0 = b * LL + c * CL;
    const int pidx = warp * 32 + lane;      // n-pair index (n0 = 2*pidx)

    float a2v0 = g_A2[d * NN + 2 * pidx];
    float a2v1 = g_A2[d * NN + 2 * pidx + 1];
    float st0 = 0.f, st1 = 0.f;

    const float4* bgp = g_bg  + (size_t)row0 * NP + pidx;
    const float2* ddp = g_ddx + (size_t)row0 * DD + d;
    const float*  xdp = g_xd  + (size_t)row0 * DD + d;
    float* outp = out + (size_t)b * LL * DD + (size_t)c * CL * DD + d;

    const unsigned fm = 0xffffffffu;
    const int bt0 = lane & 1;
    const int bt1 = (lane >> 1) & 1;
    const int bt2 = (lane >> 2) & 1;

    float4 bg[2][8];
    float2 dd[2][8];

    LOAD_BATCH(0, 0);

#pragma unroll 1
    for (int lb = 0; lb < CL; lb += 16) {
        LOAD_BATCH(1, lb + 8);
        COMPUTE_BATCH(0, lb);
        LOAD_BATCH(0, lb + 16);    // over-prefetch (padded rows cover the tail)
        COMPUTE_BATCH(1, lb + 8);
    }

    // store local end state
    *(float2*)&g_E[((size_t)bd * CC + c) * NN + 2 * pidx] = make_float2(st0, st1);

    __syncthreads();

    if (threadIdx.x < CL) {
        int l = threadIdx.x;
        float y = ypart[l] + ypart[CL + l] + ypart[2 * CL + l] + ypart[3 * CL + l];
        outp[l * DD] = y + xdp[l * DD];
    }
}

// ---------------------------------------------------------------------------
// Kernel 4 (pass C): chunk state propagation.
// S_0 = 0; S_c = E_{c-1} + exp2(a2 * dTtot_{c-1}) * S_{c-1}.
// One CTA per (b, d), thread per n.
// ---------------------------------------------------------------------------
__global__ void chain_kernel() {
    int bd = blockIdx.x;
    int d = bd & 255;
    int n = threadIdx.x;
    float a2 = g_A2[d * NN + n];
    float S = 0.f;
    size_t ebase = (size_t)bd * CC * NN + n;
#pragma unroll
    for (int c = 1; c < CC; c++) {
        float dTtot = g_cdt[(size_t)bd * LL + c * CL - 1];
        S = g_E[ebase + (size_t)(c - 1) * NN] + ex2_approx(a2 * dTtot) * S;
        g_S[ebase + (size_t)c * NN] = S;
    }
}

// ---------------------------------------------------------------------------
// Kernel 5 (pass D): correction, fully parallel over l.
// y[l] += sum_n gamma_l[n] * S_c[n] * exp2(a2[n] * cdt_l)   for chunks c>=1.
// One CTA per (b, d, c>=1); 4 warps split n (2 per lane).
// ---------------------------------------------------------------------------

#define CLOAD_BATCH(BUF, LB) do {                                             \
    _Pragma("unroll")                                                         \
    for (int k_ = 0; k_ < 8; k_++) {                                          \
        cbg[BUF][k_] = bgp[(size_t)((LB) + k_) * NP];                         \
        cdt[BUF][k_] = cdtp[(LB) + k_];                                       \
    }                                                                         \
} while (0)

#define CCOMP_BATCH(BUF, LB) do {                                             \
    float yl_[8];                                                             \
    _Pragma("unroll")                                                         \
    for (int k_ = 0; k_ < 8; k_++) {                                          \
        float dT_ = cdt[BUF][k_];                                             \
        float h0_ = ex2_approx(a2v0 * dT_) * S0;                              \
        float h1_ = ex2_approx(a2v1 * dT_) * S1;                              \
        yl_[k_] = fmaf(h0_, cbg[BUF][k_].z, h1_ * cbg[BUF][k_].w);            \
    }                                                                         \
    float v_;                                                                 \
    TREDUCE8(yl_, v_);                                                        \
    if (lane < 8) ypart[warp * CL + (LB) + lane] = v_;                        \
} while (0)

__global__ void __launch_bounds__(128) corr_kernel(float* __restrict__ out) {
    __shared__ float ypart[4 * CL];

    const int warp = threadIdx.x >> 5;
    const int lane = threadIdx.x & 31;
    const int c  = (blockIdx.x % 7) + 1;    // chunks 1..7
    const int bd = blockIdx.x / 7;
    const int b = bd >> 8;
    const int d = bd & 255;
    const int row0 = b * LL + c * CL;
    const int pidx = warp * 32 + lane;

    float a2v0 = g_A2[d * NN + 2 * pidx];
    float a2v1 = g_A2[d * NN + 2 * pidx + 1];
    float2 Sv = *(const float2*)&g_S[((size_t)bd * CC + c) * NN + 2 * pidx];
    float S0 = Sv.x, S1 = Sv.y;

    const float4* bgp  = g_bg + (size_t)row0 * NP + pidx;
    const float*  cdtp = g_cdt + (size_t)bd * LL + c * CL;
    float* outp = out + (size_t)b * LL * DD + (size_t)c * CL * DD + d;

    const unsigned fm = 0xffffffffu;
    const int bt0 = lane & 1;
    const int bt1 = (lane >> 1) & 1;
    const int bt2 = (lane >> 2) & 1;

    float4 cbg[2][8];
    float  cdt[2][8];

    CLOAD_BATCH(0, 0);

#pragma unroll 1
    for (int lb = 0; lb < CL; lb += 16) {
        CLOAD_BATCH(1, lb + 8);
        CCOMP_BATCH(0, lb);
        if (lb + 16 < CL) CLOAD_BATCH(0, lb + 16);
        CCOMP_BATCH(1, lb + 8);
    }

    __syncthreads();

    if (threadIdx.x < CL) {
        int l = threadIdx.x;
        float y = ypart[l] + ypart[CL + l] + ypart[2 * CL + l] + ypart[3 * CL + l];
        outp[l * DD] += y;
    }
}

// ---------------------------------------------------------------------------
extern "C" void kernel_launch(void* const* d_in, const int* in_sizes, int n_in,
                              void* d_out, int out_size) {
    const float* x      = (const float*)d_in[0];  // [2,512,256]
    const float* W_in   = (const float*)d_in[1];  // [256,576]
    const float* W_dt   = (const float*)d_in[2];  // [64,256]
    const float* b_dt   = (const float*)d_in[3];  // [256]
    const float* alog   = (const float*)d_in[4];  // [256,256]
    const float* delta  = (const float*)d_in[5];  // [256]
    float* out = (float*)d_out;                   // [2,512,256]

    a2_kernel<<<(DD * NN + 255) / 256, 256>>>(alog);

    dim3 pgrid(PW / 32, (BB * LL) / 32);
    dim3 pblk(32, 32);
    proj_kernel<<<pgrid, pblk>>>(x, W_in);

    dt_kernel<<<BB * LL, DD>>>(x, W_dt, b_dt, delta);
    pack_kernel<<<BB * LL, NP>>>();
    cdt_kernel<<<BB * DD / 4, 128>>>();

    scan_kernel<<<BB * DD * CC, 128>>>(out);
    chain_kernel<<<BB * DD, NN>>>();
    corr_kernel<<<BB * DD * (CC - 1), 128>>>(out);
}

// round 7
// speedup vs baseline: 1.4441x; 1.4441x over previous
#include <cuda_runtime.h>

#define BB 2
#define LL 512
#define DD 256
#define NN 256
#define DT 64
#define PW 576   // DT + 2*DD

// scratch (device globals — no allocations allowed); +16 rows padding so the
// software pipeline can over-prefetch past the end without bounds checks.
__device__ float  g_proj[(BB * LL + 16) * PW];   // [row, 576] : dt_raw | beta | gamma
__device__ float2 g_ddx [(BB * LL + 16) * DD];   // {dt, dt*x} per (row, d)
__device__ float2 g_bg2 [(BB * LL + 16) * NN];   // {beta_n, gamma_n} per (row, n)
__device__ float  g_A2  [DD * NN];               // -exp(alpha_log) * log2(e)

__device__ __forceinline__ float ex2_approx(float x) {
    float r;
    asm("ex2.approx.ftz.f32 %0, %1;" : "=f"(r) : "f"(x));
    return r;
}

// ---------------------------------------------------------------------------
// Kernel 0: A2[d][n] = -exp(alpha_log[d][n]) * log2(e)
// ---------------------------------------------------------------------------
__global__ void a2_kernel(const float* __restrict__ alog) {
    int i = blockIdx.x * blockDim.x + threadIdx.x;
    if (i < DD * NN)
        g_A2[i] = -__expf(alog[i]) * 1.4426950408889634f;
}

// ---------------------------------------------------------------------------
// Kernel 1: proj = x @ W_in   ([1024,256] x [256,576] -> [1024,576])
// ---------------------------------------------------------------------------
__global__ void proj_kernel(const float* __restrict__ x, const float* __restrict__ W) {
    __shared__ float xs[32][33];
    __shared__ float ws[32][33];
    int row = blockIdx.y * 32 + threadIdx.y;
    int col = blockIdx.x * 32 + threadIdx.x;
    float acc = 0.f;
    for (int kt = 0; kt < DD; kt += 32) {
        xs[threadIdx.y][threadIdx.x] = x[row * DD + kt + threadIdx.x];
        ws[threadIdx.y][threadIdx.x] = W[(kt + threadIdx.y) * PW + col];
        __syncthreads();
#pragma unroll
        for (int k = 0; k < 32; k++)
            acc = fmaf(xs[threadIdx.y][k], ws[k][threadIdx.x], acc);
        __syncthreads();
    }
    g_proj[row * PW + col] = acc;
}

// ---------------------------------------------------------------------------
// Kernel 2 (fused): dt = softplus(proj[:,:64] @ W_dt + b_dt); pack {dt, dt*x};
// out = x*delta (base for atomic accumulation); pack {beta, gamma} per n.
// One block per row, 256 threads (one per d == one per n).
// ---------------------------------------------------------------------------
__global__ void dt_kernel(const float* __restrict__ x, const float* __restrict__ Wdt,
                          const float* __restrict__ bdt, const float* __restrict__ delta,
                          float* __restrict__ out) {
    int r = blockIdx.x;
    int t = threadIdx.x;
    __shared__ float sp[DT];
    if (t < DT) sp[t] = g_proj[r * PW + t];
    __syncthreads();
    float acc = bdt[t];
#pragma unroll
    for (int k = 0; k < DT; k++)
        acc = fmaf(sp[k], Wdt[k * DD + t], acc);
    float dt = fmaxf(acc, 0.f) + log1pf(__expf(-fabsf(acc)));
    float xv = x[r * DD + t];
    int idx = r * DD + t;
    g_ddx[idx] = make_float2(dt, dt * xv);
    out[idx]   = xv * delta[t];
    // pack beta/gamma for n = t
    float be = g_proj[r * PW + DT + t];
    float ga = g_proj[r * PW + DT + DD + t];
    g_bg2[(size_t)r * NN + t] = make_float2(be, ga);
}

// ---------------------------------------------------------------------------
// Kernel 3: sequential scan.
// Two CTAs per (b, d); each CTA's 4 warps cover 128 n (1 n per lane).
// 8-step double-buffered batches (2 LDG per step). Per-warp partial y's go to
// private smem columns; final combine atomically adds into out (pre-init x*d).
// ---------------------------------------------------------------------------

#define LOAD_BATCH(BUF, LB) do {                                              \
    _Pragma("unroll")                                                         \
    for (int k_ = 0; k_ < 8; k_++) {                                          \
        bg[BUF][k_] = bgp[(size_t)((LB) + k_) * NN];                          \
        dd[BUF][k_] = ddp[(size_t)((LB) + k_) * DD];                          \
    }                                                                         \
} while (0)

// transposed reduction over 32 lanes: Y[k]=sum_lanes yl_[k]; Y[lane&7] -> VOUT
#define TREDUCE8(YL, VOUT) do {                                               \
    float s_, r0_, r1_, r2_, r3_, q0_, q1_;                                   \
    s_  = bt0 ? YL[0] : YL[1];                                                \
    r0_ = (bt0 ? YL[1] : YL[0]) + __shfl_xor_sync(fm, s_, 1);                 \
    s_  = bt0 ? YL[2] : YL[3];                                                \
    r1_ = (bt0 ? YL[3] : YL[2]) + __shfl_xor_sync(fm, s_, 1);                 \
    s_  = bt0 ? YL[4] : YL[5];                                                \
    r2_ = (bt0 ? YL[5] : YL[4]) + __shfl_xor_sync(fm, s_, 1);                 \
    s_  = bt0 ? YL[6] : YL[7];                                                \
    r3_ = (bt0 ? YL[7] : YL[6]) + __shfl_xor_sync(fm, s_, 1);                 \
    s_  = bt1 ? r0_ : r1_;                                                    \
    q0_ = (bt1 ? r1_ : r0_) + __shfl_xor_sync(fm, s_, 2);                     \
    s_  = bt1 ? r2_ : r3_;                                                    \
    q1_ = (bt1 ? r3_ : r2_) + __shfl_xor_sync(fm, s_, 2);                     \
    s_  = bt2 ? q0_ : q1_;                                                    \
    VOUT = (bt2 ? q1_ : q0_) + __shfl_xor_sync(fm, s_, 4);                    \
    VOUT += __shfl_xor_sync(fm, VOUT, 8);                                     \
    VOUT += __shfl_xor_sync(fm, VOUT, 16);                                    \
} while (0)

#define COMPUTE_BATCH(BUF, LB) do {                                           \
    float yl_[8];                                                             \
    _Pragma("unroll")                                                         \
    for (int k_ = 0; k_ < 8; k_++) {                                          \
        float dt_  = dd[BUF][k_].x;                                           \
        float dtx_ = dd[BUF][k_].y;                                           \
        float a_ = ex2_approx(dt_ * a2v);                                     \
        st = fmaf(a_, st, dtx_ * bg[BUF][k_].x);                              \
        yl_[k_] = st * bg[BUF][k_].y;                                         \
    }                                                                         \
    float v_;                                                                 \
    TREDUCE8(yl_, v_);                                                        \
    if (lane < 8) ypart[warp * LL + (LB) + lane] = v_;                        \
} while (0)

__global__ void __launch_bounds__(128) scan_kernel(float* __restrict__ out) {
    __shared__ float ypart[4 * LL];   // [warp][l], 8 KB

    const int warp = threadIdx.x >> 5;
    const int lane = threadIdx.x & 31;
    const int half = blockIdx.x & 1;        // n-half
    const int bd = blockIdx.x >> 1;
    const int b = bd >> 8;
    const int d = bd & 255;
    const int n = half * 128 + warp * 32 + lane;

    float a2v = g_A2[d * NN + n];
    float st = 0.f;

    const float2* bgp = g_bg2 + (size_t)(b * LL) * NN + n;
    const float2* ddp = g_ddx + (size_t)(b * LL) * DD + d;
    float* outp = out + (size_t)b * LL * DD + d;

    const unsigned fm = 0xffffffffu;
    const int bt0 = lane & 1;
    const int bt1 = (lane >> 1) & 1;
    const int bt2 = (lane >> 2) & 1;

    // double-buffered operand stages (constant-indexed register arrays)
    float2 bg[2][8];
    float2 dd[2][8];

    LOAD_BATCH(0, 0);

#pragma unroll 1
    for (int lb = 0; lb < LL; lb += 16) {
        LOAD_BATCH(1, lb + 8);
        COMPUTE_BATCH(0, lb);
        LOAD_BATCH(0, lb + 16);    // over-prefetch into padded rows at the end
        COMPUTE_BATCH(1, lb + 8);
    }

    __syncthreads();

    // combine this CTA's 4 warp-partials, atomically add into out
#pragma unroll
    for (int i = 0; i < 4; i++) {
        int l = threadIdx.x + i * 128;
        float y = ypart[l] + ypart[LL + l] + ypart[2 * LL + l] + ypart[3 * LL + l];
        atomicAdd(&outp[l * DD], y);
    }
}

// ---------------------------------------------------------------------------
extern "C" void kernel_launch(void* const* d_in, const int* in_sizes, int n_in,
                              void* d_out, int out_size) {
    const float* x      = (const float*)d_in[0];  // [2,512,256]
    const float* W_in   = (const float*)d_in[1];  // [256,576]
    const float* W_dt   = (const float*)d_in[2];  // [64,256]
    const float* b_dt   = (const float*)d_in[3];  // [256]
    const float* alog   = (const float*)d_in[4];  // [256,256]
    const float* delta  = (const float*)d_in[5];  // [256]
    float* out = (float*)d_out;                   // [2,512,256]

    a2_kernel<<<(DD * NN + 255) / 256, 256>>>(alog);

    dim3 pgrid(PW / 32, (BB * LL) / 32);
    dim3 pblk(32, 32);
    proj_kernel<<<pgrid, pblk>>>(x, W_in);

    dt_kernel<<<BB * LL, 256>>>(x, W_dt, b_dt, delta, out);

    scan_kernel<<<BB * DD * 2, 128>>>(out);
}

// round 8
// speedup vs baseline: 1.9958x; 1.3820x over previous
#include <cuda_runtime.h>

#define BB 2
#define LL 512
#define DD 256
#define NN 256
#define DT 64
#define PW 576   // DT + 2*DD

// scratch (device globals — no allocations allowed); +16 rows padding so the
// software pipeline can over-prefetch past the end without bounds checks.
__device__ float  g_proj[(BB * LL + 16) * PW];   // [row, 576] : dt_raw | beta | gamma
__device__ float2 g_ddx [(BB * LL + 16) * DD];   // {dt, dt*x} per (row, d)
__device__ float2 g_bg2 [(BB * LL + 16) * NN];   // {beta_n, gamma_n} per (row, n)

__device__ __forceinline__ float ex2_approx(float x) {
    float r;
    asm("ex2.approx.ftz.f32 %0, %1;" : "=f"(r) : "f"(x));
    return r;
}

// ---------------------------------------------------------------------------
// Kernel 1: proj = x @ W_in   ([1024,256] x [256,576] -> [1024,576])
// 64x64x16 register-blocked tiles, 256 threads, 4x4 micro-tile per thread.
// grid (576/64=9, 1024/64=16) = 144 CTAs ~= one full wave.
// ---------------------------------------------------------------------------
__global__ void __launch_bounds__(256) proj_kernel(const float* __restrict__ x,
                                                   const float* __restrict__ W) {
    __shared__ float xs[16][65];   // [k][m], padded (scalar stores)
    __shared__ float ws[16][64];   // [k][n], float4 stores
    const int bm = blockIdx.y * 64;
    const int bn = blockIdx.x * 64;
    const int tid = threadIdx.x;
    const int tx = tid & 15;       // n-tile
    const int ty = tid >> 4;       // m-tile

    float acc[4][4] = {};

    for (int k0 = 0; k0 < DD; k0 += 16) {
        // load x block [64 rows x 16 k] -> xs[k][m] (transposed)
        {
            int r = tid >> 2;            // 0..63
            int c = (tid & 3) * 4;       // 0,4,8,12
            float4 v = *(const float4*)&x[(size_t)(bm + r) * DD + k0 + c];
            xs[c + 0][r] = v.x; xs[c + 1][r] = v.y;
            xs[c + 2][r] = v.z; xs[c + 3][r] = v.w;
        }
        // load W block [16 k x 64 cols] -> ws[k][n]
        {
            int k = tid >> 4;            // 0..15
            int c = (tid & 15) * 4;      // 0..60
            *(float4*)&ws[k][c] = *(const float4*)&W[(size_t)(k0 + k) * PW + bn + c];
        }
        __syncthreads();
#pragma unroll
        for (int k = 0; k < 16; k++) {
            float a[4], bv[4];
#pragma unroll
            for (int i = 0; i < 4; i++) a[i] = xs[k][ty * 4 + i];
#pragma unroll
            for (int j = 0; j < 4; j++) bv[j] = ws[k][tx * 4 + j];
#pragma unroll
            for (int i = 0; i < 4; i++)
#pragma unroll
                for (int j = 0; j < 4; j++)
                    acc[i][j] = fmaf(a[i], bv[j], acc[i][j]);
        }
        __syncthreads();
    }

#pragma unroll
    for (int i = 0; i < 4; i++) {
        float4 v = make_float4(acc[i][0], acc[i][1], acc[i][2], acc[i][3]);
        *(float4*)&g_proj[(size_t)(bm + ty * 4 + i) * PW + bn + tx * 4] = v;
    }
}

// ---------------------------------------------------------------------------
// Kernel 2 (fused): dt = softplus(proj[:,:64] @ W_dt + b_dt); pack {dt, dt*x};
// out = x*delta (base for atomic accumulation); pack {beta, gamma} per n.
// One block per row, 256 threads (one per d == one per n).
// ---------------------------------------------------------------------------
__global__ void dt_kernel(const float* __restrict__ x, const float* __restrict__ Wdt,
                          const float* __restrict__ bdt, const float* __restrict__ delta,
                          float* __restrict__ out) {
    int r = blockIdx.x;
    int t = threadIdx.x;
    __shared__ float sp[DT];
    if (t < DT) sp[t] = g_proj[r * PW + t];
    __syncthreads();
    float acc = bdt[t];
#pragma unroll
    for (int k = 0; k < DT; k++)
        acc = fmaf(sp[k], Wdt[k * DD + t], acc);
    float dt = fmaxf(acc, 0.f) + log1pf(__expf(-fabsf(acc)));
    float xv = x[r * DD + t];
    int idx = r * DD + t;
    g_ddx[idx] = make_float2(dt, dt * xv);
    out[idx]   = xv * delta[t];
    // pack beta/gamma for n = t
    float be = g_proj[r * PW + DT + t];
    float ga = g_proj[r * PW + DT + DD + t];
    g_bg2[(size_t)r * NN + t] = make_float2(be, ga);
}

// ---------------------------------------------------------------------------
// Kernel 3: sequential scan.
// Two CTAs per (b, d); each CTA's 4 warps cover 128 n (1 n per lane).
// 8-step double-buffered batches (2 LDG per step). Per-warp partial y's go to
// private smem columns; final combine atomically adds into out (pre-init x*d).
// a2 = -exp(alpha_log)*log2e computed inline (one value per thread).
// ---------------------------------------------------------------------------

#define LOAD_BATCH(BUF, LB) do {                                              \
    _Pragma("unroll")                                                         \
    for (int k_ = 0; k_ < 8; k_++) {                                          \
        bg[BUF][k_] = bgp[(size_t)((LB) + k_) * NN];                          \
        dd[BUF][k_] = ddp[(size_t)((LB) + k_) * DD];                          \
    }                                                                         \
} while (0)

// transposed reduction over 32 lanes: Y[k]=sum_lanes yl_[k]; Y[lane&7] -> VOUT
#define TREDUCE8(YL, VOUT) do {                                               \
    float s_, r0_, r1_, r2_, r3_, q0_, q1_;                                   \
    s_  = bt0 ? YL[0] : YL[1];                                                \
    r0_ = (bt0 ? YL[1] : YL[0]) + __shfl_xor_sync(fm, s_, 1);                 \
    s_  = bt0 ? YL[2] : YL[3];                                                \
    r1_ = (bt0 ? YL[3] : YL[2]) + __shfl_xor_sync(fm, s_, 1);                 \
    s_  = bt0 ? YL[4] : YL[5];                                                \
    r2_ = (bt0 ? YL[5] : YL[4]) + __shfl_xor_sync(fm, s_, 1);                 \
    s_  = bt0 ? YL[6] : YL[7];                                                \
    r3_ = (bt0 ? YL[7] : YL[6]) + __shfl_xor_sync(fm, s_, 1);                 \
    s_  = bt1 ? r0_ : r1_;                                                    \
    q0_ = (bt1 ? r1_ : r0_) + __shfl_xor_sync(fm, s_, 2);                     \
    s_  = bt1 ? r2_ : r3_;                                                    \
    q1_ = (bt1 ? r3_ : r2_) + __shfl_xor_sync(fm, s_, 2);                     \
    s_  = bt2 ? q0_ : q1_;                                                    \
    VOUT = (bt2 ? q1_ : q0_) + __shfl_xor_sync(fm, s_, 4);                    \
    VOUT += __shfl_xor_sync(fm, VOUT, 8);                                     \
    VOUT += __shfl_xor_sync(fm, VOUT, 16);                                    \
} while (0)

#define COMPUTE_BATCH(BUF, LB) do {                                           \
    float yl_[8];                                                             \
    _Pragma("unroll")                                                         \
    for (int k_ = 0; k_ < 8; k_++) {                                          \
        float dt_  = dd[BUF][k_].x;                                           \
        float dtx_ = dd[BUF][k_].y;                                           \
        float a_ = ex2_approx(dt_ * a2v);                                     \
        st = fmaf(a_, st, dtx_ * bg[BUF][k_].x);                              \
        yl_[k_] = st * bg[BUF][k_].y;                                         \
    }                                                                         \
    float v_;                                                                 \
    TREDUCE8(yl_, v_);                                                        \
    if (lane < 8) ypart[warp * LL + (LB) + lane] = v_;                        \
} while (0)

__global__ void __launch_bounds__(128) scan_kernel(float* __restrict__ out,
                                                   const float* __restrict__ alog) {
    __shared__ float ypart[4 * LL];   // [warp][l], 8 KB

    const int warp = threadIdx.x >> 5;
    const int lane = threadIdx.x & 31;
    const int half = blockIdx.x & 1;        // n-half
    const int bd = blockIdx.x >> 1;
    const int b = bd >> 8;
    const int d = bd & 255;
    const int n = half * 128 + warp * 32 + lane;

    float a2v = -__expf(alog[d * NN + n]) * 1.4426950408889634f;
    float st = 0.f;

    const float2* bgp = g_bg2 + (size_t)(b * LL) * NN + n;
    const float2* ddp = g_ddx + (size_t)(b * LL) * DD + d;
    float* outp = out + (size_t)b * LL * DD + d;

    const unsigned fm = 0xffffffffu;
    const int bt0 = lane & 1;
    const int bt1 = (lane >> 1) & 1;
    const int bt2 = (lane >> 2) & 1;

    // double-buffered operand stages (constant-indexed register arrays)
    float2 bg[2][8];
    float2 dd[2][8];

    LOAD_BATCH(0, 0);

#pragma unroll 1
    for (int lb = 0; lb < LL; lb += 16) {
        LOAD_BATCH(1, lb + 8);
        COMPUTE_BATCH(0, lb);
        LOAD_BATCH(0, lb + 16);    // over-prefetch into padded rows at the end
        COMPUTE_BATCH(1, lb + 8);
    }

    __syncthreads();

    // combine this CTA's 4 warp-partials, atomically add into out
#pragma unroll
    for (int i = 0; i < 4; i++) {
        int l = threadIdx.x + i * 128;
        float y = ypart[l] + ypart[LL + l] + ypart[2 * LL + l] + ypart[3 * LL + l];
        atomicAdd(&outp[l * DD], y);
    }
}

// ---------------------------------------------------------------------------
extern "C" void kernel_launch(void* const* d_in, const int* in_sizes, int n_in,
                              void* d_out, int out_size) {
    const float* x      = (const float*)d_in[0];  // [2,512,256]
    const float* W_in   = (const float*)d_in[1];  // [256,576]
    const float* W_dt   = (const float*)d_in[2];  // [64,256]
    const float* b_dt   = (const float*)d_in[3];  // [256]
    const float* alog   = (const float*)d_in[4];  // [256,256]
    const float* delta  = (const float*)d_in[5];  // [256]
    float* out = (float*)d_out;                   // [2,512,256]

    dim3 pgrid(PW / 64, (BB * LL) / 64);
    proj_kernel<<<pgrid, 256>>>(x, W_in);

    dt_kernel<<<BB * LL, 256>>>(x, W_dt, b_dt, delta, out);

    scan_kernel<<<BB * DD * 2, 128>>>(out, alog);
}

// round 9
// speedup vs baseline: 2.1224x; 1.0635x over previous
#include <cuda_runtime.h>

#define BB 2
#define LL 512
#define DD 256
#define NN 256
#define DT 64
#define PW 576   // DT + 2*DD

// scratch (device globals — no allocations allowed); +16 rows padding so the
// software pipeline can over-prefetch past the end without bounds checks.
__device__ float  g_proj[(BB * LL + 16) * PW];   // [row, 576] : dt_raw | beta | gamma
__device__ float2 g_ddx [(BB * LL + 16) * DD];   // {dt, dt*x} per (row, d)
__device__ float2 g_bg2 [(BB * LL + 16) * NN];   // {beta_n, gamma_n} per (row, n)

__device__ __forceinline__ float ex2_approx(float x) {
    float r;
    asm("ex2.approx.ftz.f32 %0, %1;" : "=f"(r) : "f"(x));
    return r;
}

// ---------------------------------------------------------------------------
// Kernel 1: proj = x @ W_in   ([1024,256] x [256,576] -> [1024,576])
// 64x64 tiles, kc=32, double-buffered smem, 256 threads, 4x4 micro-tile.
// Loads for chunk i+1 are issued into registers before computing chunk i;
// one __syncthreads per chunk (8 total).
// ---------------------------------------------------------------------------
__global__ void __launch_bounds__(256) proj_kernel(const float* __restrict__ x,
                                                   const float* __restrict__ W) {
    __shared__ float xs[2][32][68];   // [buf][k][m], padded to 68 (16B-aligned rows)
    __shared__ float ws[2][32][64];   // [buf][k][n]
    const int bm = blockIdx.y * 64;
    const int bn = blockIdx.x * 64;
    const int tid = threadIdx.x;
    const int tx = tid & 15;          // n micro-tile
    const int ty = tid >> 4;          // m micro-tile

    // load-role indices
    const int xr = tid >> 2;          // 0..63  (m row)
    const int xc = (tid & 3) * 8;     // 0,8,16,24 (k base; two float4)
    const int wr = tid >> 3;          // 0..31  (k row)
    const int wc = (tid & 7) * 8;     // 0..56  (n base; two float4)

    float acc[4][4] = {};

    // prologue: load chunk 0 into buf 0
    {
        float4 a0 = *(const float4*)&x[(size_t)(bm + xr) * DD + 0 + xc];
        float4 a1 = *(const float4*)&x[(size_t)(bm + xr) * DD + 0 + xc + 4];
        xs[0][xc + 0][xr] = a0.x; xs[0][xc + 1][xr] = a0.y;
        xs[0][xc + 2][xr] = a0.z; xs[0][xc + 3][xr] = a0.w;
        xs[0][xc + 4][xr] = a1.x; xs[0][xc + 5][xr] = a1.y;
        xs[0][xc + 6][xr] = a1.z; xs[0][xc + 7][xr] = a1.w;
        *(float4*)&ws[0][wr][wc]     = *(const float4*)&W[(size_t)(0 + wr) * PW + bn + wc];
        *(float4*)&ws[0][wr][wc + 4] = *(const float4*)&W[(size_t)(0 + wr) * PW + bn + wc + 4];
    }
    __syncthreads();

#pragma unroll
    for (int ch = 0; ch < 8; ch++) {
        const int cur = ch & 1;
        const int nxt = cur ^ 1;
        const int k1 = (ch + 1) * 32;

        // issue next chunk's global loads (registers) before compute
        float4 a0, a1, w0, w1;
        if (ch < 7) {
            a0 = *(const float4*)&x[(size_t)(bm + xr) * DD + k1 + xc];
            a1 = *(const float4*)&x[(size_t)(bm + xr) * DD + k1 + xc + 4];
            w0 = *(const float4*)&W[(size_t)(k1 + wr) * PW + bn + wc];
            w1 = *(const float4*)&W[(size_t)(k1 + wr) * PW + bn + wc + 4];
        }

        // compute current chunk (512 FFMA per thread — covers the LDG latency)
#pragma unroll
        for (int k = 0; k < 32; k++) {
            float4 av = *(const float4*)&xs[cur][k][ty * 4];
            float4 bv = *(const float4*)&ws[cur][k][tx * 4];
            float a_[4] = {av.x, av.y, av.z, av.w};
            float b_[4] = {bv.x, bv.y, bv.z, bv.w};
#pragma unroll
            for (int i = 0; i < 4; i++)
#pragma unroll
                for (int j = 0; j < 4; j++)
                    acc[i][j] = fmaf(a_[i], b_[j], acc[i][j]);
        }

        // stage next chunk into the other buffer
        if (ch < 7) {
            xs[nxt][xc + 0][xr] = a0.x; xs[nxt][xc + 1][xr] = a0.y;
            xs[nxt][xc + 2][xr] = a0.z; xs[nxt][xc + 3][xr] = a0.w;
            xs[nxt][xc + 4][xr] = a1.x; xs[nxt][xc + 5][xr] = a1.y;
            xs[nxt][xc + 6][xr] = a1.z; xs[nxt][xc + 7][xr] = a1.w;
            *(float4*)&ws[nxt][wr][wc]     = w0;
            *(float4*)&ws[nxt][wr][wc + 4] = w1;
            __syncthreads();
        }
    }

#pragma unroll
    for (int i = 0; i < 4; i++) {
        float4 v = make_float4(acc[i][0], acc[i][1], acc[i][2], acc[i][3]);
        *(float4*)&g_proj[(size_t)(bm + ty * 4 + i) * PW + bn + tx * 4] = v;
    }
}

// ---------------------------------------------------------------------------
// Kernel 2 (fused): dt = softplus(proj[:,:64] @ W_dt + b_dt); pack {dt, dt*x};
// out = x*delta (base for atomic accumulation); pack {beta, gamma} per n.
// One block per row, 256 threads (one per d == one per n).
// ---------------------------------------------------------------------------
__global__ void dt_kernel(const float* __restrict__ x, const float* __restrict__ Wdt,
                          const float* __restrict__ bdt, const float* __restrict__ delta,
                          float* __restrict__ out) {
    int r = blockIdx.x;
    int t = threadIdx.x;
    __shared__ float sp[DT];
    if (t < DT) sp[t] = g_proj[r * PW + t];
    __syncthreads();
    float acc = bdt[t];
#pragma unroll
    for (int k = 0; k < DT; k++)
        acc = fmaf(sp[k], Wdt[k * DD + t], acc);
    float dt = fmaxf(acc, 0.f) + log1pf(__expf(-fabsf(acc)));
    float xv = x[r * DD + t];
    int idx = r * DD + t;
    g_ddx[idx] = make_float2(dt, dt * xv);
    out[idx]   = xv * delta[t];
    // pack beta/gamma for n = t
    float be = g_proj[r * PW + DT + t];
    float ga = g_proj[r * PW + DT + DD + t];
    g_bg2[(size_t)r * NN + t] = make_float2(be, ga);
}

// ---------------------------------------------------------------------------
// Kernel 3: sequential scan.
// Two CTAs per (b, d); each CTA's 4 warps cover 128 n (1 n per lane).
// 8-step double-buffered batches (2 LDG per step). Per-warp partial y's go to
// private smem columns; final combine atomically adds into out (pre-init x*d).
// a2 = -exp(alpha_log)*log2e computed inline (one value per thread).
// ---------------------------------------------------------------------------

#define LOAD_BATCH(BUF, LB) do {                                              \
    _Pragma("unroll")                                                         \
    for (int k_ = 0; k_ < 8; k_++) {                                          \
        bg[BUF][k_] = bgp[(size_t)((LB) + k_) * NN];                          \
        dd[BUF][k_] = ddp[(size_t)((LB) + k_) * DD];                          \
    }                                                                         \
} while (0)

// transposed reduction over 32 lanes: Y[k]=sum_lanes yl_[k]; Y[lane&7] -> VOUT
#define TREDUCE8(YL, VOUT) do {                                               \
    float s_, r0_, r1_, r2_, r3_, q0_, q1_;                                   \
    s_  = bt0 ? YL[0] : YL[1];                                                \
    r0_ = (bt0 ? YL[1] : YL[0]) + __shfl_xor_sync(fm, s_, 1);                 \
    s_  = bt0 ? YL[2] : YL[3];                                                \
    r1_ = (bt0 ? YL[3] : YL[2]) + __shfl_xor_sync(fm, s_, 1);                 \
    s_  = bt0 ? YL[4] : YL[5];                                                \
    r2_ = (bt0 ? YL[5] : YL[4]) + __shfl_xor_sync(fm, s_, 1);                 \
    s_  = bt0 ? YL[6] : YL[7];                                                \
    r3_ = (bt0 ? YL[7] : YL[6]) + __shfl_xor_sync(fm, s_, 1);                 \
    s_  = bt1 ? r0_ : r1_;                                                    \
    q0_ = (bt1 ? r1_ : r0_) + __shfl_xor_sync(fm, s_, 2);                     \
    s_  = bt1 ? r2_ : r3_;                                                    \
    q1_ = (bt1 ? r3_ : r2_) + __shfl_xor_sync(fm, s_, 2);                     \
    s_  = bt2 ? q0_ : q1_;                                                    \
    VOUT = (bt2 ? q1_ : q0_) + __shfl_xor_sync(fm, s_, 4);                    \
    VOUT += __shfl_xor_sync(fm, VOUT, 8);                                     \
    VOUT += __shfl_xor_sync(fm, VOUT, 16);                                    \
} while (0)

#define COMPUTE_BATCH(BUF, LB) do {                                           \
    float yl_[8];                                                             \
    _Pragma("unroll")                                                         \
    for (int k_ = 0; k_ < 8; k_++) {                                          \
        float dt_  = dd[BUF][k_].x;                                           \
        float dtx_ = dd[BUF][k_].y;                                           \
        float a_ = ex2_approx(dt_ * a2v);                                     \
        st = fmaf(a_, st, dtx_ * bg[BUF][k_].x);                              \
        yl_[k_] = st * bg[BUF][k_].y;                                         \
    }                                                                         \
    float v_;                                                                 \
    TREDUCE8(yl_, v_);                                                        \
    if (lane < 8) ypart[warp * LL + (LB) + lane] = v_;                        \
} while (0)

__global__ void __launch_bounds__(128) scan_kernel(float* __restrict__ out,
                                                   const float* __restrict__ alog) {
    __shared__ float ypart[4 * LL];   // [warp][l], 8 KB

    const int warp = threadIdx.x >> 5;
    const int lane = threadIdx.x & 31;
    const int half = blockIdx.x & 1;        // n-half
    const int bd = blockIdx.x >> 1;
    const int b = bd >> 8;
    const int d = bd & 255;
    const int n = half * 128 + warp * 32 + lane;

    float a2v = -__expf(alog[d * NN + n]) * 1.4426950408889634f;
    float st = 0.f;

    const float2* bgp = g_bg2 + (size_t)(b * LL) * NN + n;
    const float2* ddp = g_ddx + (size_t)(b * LL) * DD + d;
    float* outp = out + (size_t)b * LL * DD + d;

    const unsigned fm = 0xffffffffu;
    const int bt0 = lane & 1;
    const int bt1 = (lane >> 1) & 1;
    const int bt2 = (lane >> 2) & 1;

    // double-buffered operand stages (constant-indexed register arrays)
    float2 bg[2][8];
    float2 dd[2][8];

    LOAD_BATCH(0, 0);

#pragma unroll 1
    for (int lb = 0; lb < LL; lb += 16) {
        LOAD_BATCH(1, lb + 8);
        COMPUTE_BATCH(0, lb);
        LOAD_BATCH(0, lb + 16);    // over-prefetch into padded rows at the end
        COMPUTE_BATCH(1, lb + 8);
    }

    __syncthreads();

    // combine this CTA's 4 warp-partials, atomically add into out
#pragma unroll
    for (int i = 0; i < 4; i++) {
        int l = threadIdx.x + i * 128;
        float y = ypart[l] + ypart[LL + l] + ypart[2 * LL + l] + ypart[3 * LL + l];
        atomicAdd(&outp[l * DD], y);
    }
}

// ---------------------------------------------------------------------------
extern "C" void kernel_launch(void* const* d_in, const int* in_sizes, int n_in,
                              void* d_out, int out_size) {
    const float* x      = (const float*)d_in[0];  // [2,512,256]
    const float* W_in   = (const float*)d_in[1];  // [256,576]
    const float* W_dt   = (const float*)d_in[2];  // [64,256]
    const float* b_dt   = (const float*)d_in[3];  // [256]
    const float* alog   = (const float*)d_in[4];  // [256,256]
    const float* delta  = (const float*)d_in[5];  // [256]
    float* out = (float*)d_out;                   // [2,512,256]

    dim3 pgrid(PW / 64, (BB * LL) / 64);
    proj_kernel<<<pgrid, 256>>>(x, W_in);

    dt_kernel<<<BB * LL, 256>>>(x, W_dt, b_dt, delta, out);

    scan_kernel<<<BB * DD * 2, 128>>>(out, alog);
}